// round 8
// baseline (speedup 1.0000x reference)
#include <cuda_runtime.h>
#include <cuda_bf16.h>
#include <cstdint>
#include <math.h>

#define CH 192
#define DD 24
#define BB 8
#define LL 4096
#define NTOK (BB*LL)
#define BQ 128
#define BK 256
#define NKT (LL/BK)
#define NS 2
#define KT_PER (NKT/NS)

#define QPAD 28
#define KPAD 28
#define VROW 132                      // u32 words per d-row (128 + 4 pad)
#define LOG2E 1.4426950408889634f

// smem float offsets (attn kernel): K region doubles as Q stage + output bounce
#define OFF_K 0                       // 256*28 = 7168 floats
#define OFF_V 7168                    // 32*132 = 4224 words
#define SM_FLOATS (OFF_V + 4224)      // 11392 floats = 45568 B

__device__ float g_q[NTOK*DD];
__device__ float g_k[NTOK*DD];
__device__ uint32_t g_vtp[BB*DD*(LL/2)];   // [b][d][key/2] bf16x2 key-pair words
__device__ float g_part[NS*NTOK*28];       // unnormalized o[24] + l @ [24]

// ---------------------------------------------------------------------------
// helpers
// ---------------------------------------------------------------------------
__device__ __forceinline__ void mma_tf32(float* c, const uint32_t* a, uint32_t b0, uint32_t b1){
    asm volatile("mma.sync.aligned.m16n8k8.row.col.f32.tf32.tf32.f32 "
        "{%0,%1,%2,%3}, {%4,%5,%6,%7}, {%8,%9}, {%0,%1,%2,%3};"
        : "+f"(c[0]), "+f"(c[1]), "+f"(c[2]), "+f"(c[3])
        : "r"(a[0]), "r"(a[1]), "r"(a[2]), "r"(a[3]), "r"(b0), "r"(b1));
}
__device__ __forceinline__ void mma_bf16(float* c, const uint32_t* a, uint32_t b0, uint32_t b1){
    asm volatile("mma.sync.aligned.m16n8k16.row.col.f32.bf16.bf16.f32 "
        "{%0,%1,%2,%3}, {%4,%5,%6,%7}, {%8,%9}, {%0,%1,%2,%3};"
        : "+f"(c[0]), "+f"(c[1]), "+f"(c[2]), "+f"(c[3])
        : "r"(a[0]), "r"(a[1]), "r"(a[2]), "r"(a[3]), "r"(b0), "r"(b1));
}
__device__ __forceinline__ uint32_t packbf(float hi, float lo){
    uint32_t r;
    asm("cvt.rn.bf16x2.f32 %0, %1, %2;" : "=r"(r) : "f"(hi), "f"(lo));
    return r;
}
__device__ __forceinline__ float ex2f(float x){
    float y;
    asm("ex2.approx.f32 %0, %1;" : "=f"(y) : "f"(x));
    return y;
}
__device__ __forceinline__ uint32_t smem_u32(const void* p){
    uint32_t a;
    asm("{ .reg .u64 t; cvta.to.shared.u64 t, %1; cvt.u32.u64 %0, t; }":"=r"(a):"l"(p));
    return a;
}
__device__ __forceinline__ void cp16(uint32_t dst, const void* src){
    asm volatile("cp.async.ca.shared.global [%0], [%1], 16;"::"r"(dst),"l"(src):"memory");
}
#define CP_COMMIT() asm volatile("cp.async.commit_group;":::"memory")
#define CP_WAIT0()  asm volatile("cp.async.wait_group 0;":::"memory")

// ---------------------------------------------------------------------------
// Kernel 1: fused QKV projection; V written transposed+packed bf16 pairs.
// ---------------------------------------------------------------------------
__global__ __launch_bounds__(128) void proj_kernel(
    const float* __restrict__ x, const float* __restrict__ wq,
    const float* __restrict__ wk, const float* __restrict__ wv)
{
    extern __shared__ float Ws[];    // reused as Vt[24][128] after compute
    int tid = threadIdx.x;
    for (int i = tid; i < CH*DD; i += 128) {
        int c = i / DD, d = i - c*DD;
        Ws[c*72 + d]      = wq[i];
        Ws[c*72 + 24 + d] = wk[i];
        Ws[c*72 + 48 + d] = wv[i];
    }
    __syncthreads();

    int tok = blockIdx.x * 128 + tid;
    float acc[72];
    #pragma unroll
    for (int o = 0; o < 72; o++) acc[o] = 0.f;

    const float4* xr = reinterpret_cast<const float4*>(x + (size_t)tok * CH);
    #pragma unroll 1
    for (int c4 = 0; c4 < CH/4; c4++) {
        float4 xv = xr[c4];
        float xs[4] = {xv.x, xv.y, xv.z, xv.w};
        #pragma unroll
        for (int j = 0; j < 4; j++) {
            const float4* wrow = reinterpret_cast<const float4*>(Ws + (c4*4 + j)*72);
            #pragma unroll
            for (int o4 = 0; o4 < 18; o4++) {
                float4 w = wrow[o4];
                acc[o4*4+0] = fmaf(xs[j], w.x, acc[o4*4+0]);
                acc[o4*4+1] = fmaf(xs[j], w.y, acc[o4*4+1]);
                acc[o4*4+2] = fmaf(xs[j], w.z, acc[o4*4+2]);
                acc[o4*4+3] = fmaf(xs[j], w.w, acc[o4*4+3]);
            }
        }
    }

    float4* qo = reinterpret_cast<float4*>(g_q + (size_t)tok * DD);
    float4* ko = reinterpret_cast<float4*>(g_k + (size_t)tok * DD);
    #pragma unroll
    for (int i = 0; i < 6; i++) {
        qo[i] = make_float4(acc[i*4+0],    acc[i*4+1],    acc[i*4+2],    acc[i*4+3]);
        ko[i] = make_float4(acc[24+i*4+0], acc[24+i*4+1], acc[24+i*4+2], acc[24+i*4+3]);
    }

    // ---- V: smem transpose then packed bf16x2 key-pair words ----
    __syncthreads();
    float* Vt = Ws;                  // [24][128]
    #pragma unroll
    for (int d = 0; d < DD; d++) Vt[d*128 + tid] = acc[48 + d];
    __syncthreads();

    int gb   = blockIdx.x * 128;
    int b0   = gb / LL;
    int koff = (gb - b0*LL) / 2;
    uint32_t* dst = g_vtp + (size_t)b0*DD*(LL/2) + koff;
    #pragma unroll
    for (int i = 0; i < 12; i++) {
        int idx = tid + i*128;       // < 1536
        int d = idx >> 6, p = idx & 63;
        dst[(size_t)d*(LL/2) + p] = packbf(Vt[d*128 + 2*p + 1], Vt[d*128 + 2*p]);
    }
}

// ---------------------------------------------------------------------------
// Kernel 2: split-K mma.sync flash attention (max-free softmax).
// grid (32, 8, NS); each block: 128 queries x (LL/NS) keys -> partial (o, l).
// ---------------------------------------------------------------------------
__global__ __launch_bounds__(128, 3) void attn_mma_kernel()
{
    extern __shared__ float sm[];
    float* Ks = sm + OFF_K;                      // also Q stage + bounce
    uint32_t* Vbw = reinterpret_cast<uint32_t*>(sm + OFF_V);
    const uint32_t* Vb = Vbw;
    const uint32_t smb = smem_u32(sm);

    const int tid  = threadIdx.x;
    const int w    = tid >> 5;
    const int lane = tid & 31;
    const int g    = lane >> 2;
    const int tig  = lane & 3;
    const int qt = blockIdx.x, b = blockIdx.y, sp = blockIdx.z;

    // ---- stage Q tile (scaled by log2 e) into the K region ----
    {
        const float4* src = reinterpret_cast<const float4*>(g_q + (size_t)(b*LL + qt*BQ + tid)*DD);
        float4* dst = reinterpret_cast<float4*>(Ks + tid*QPAD);
        #pragma unroll
        for (int i = 0; i < 6; i++) {
            float4 t = src[i];
            t.x *= LOG2E; t.y *= LOG2E; t.z *= LOG2E; t.w *= LOG2E;
            dst[i] = t;
        }
    }
    // ---- static V rows 24..31: zero, then row 24 = bf16 ones (same-thread order) ----
    for (int i = tid; i < 8*VROW; i += 128) Vbw[24*VROW + i] = 0;
    Vbw[24*VROW + tid] = 0x3F803F80u;     // tid<128 == cols 0..127 of row 24
    __syncthreads();

    // ---- Q fragments: warp owns 32 rows (2 m-tiles) ----
    uint32_t qa[2][3][4];
    #pragma unroll
    for (int mt = 0; mt < 2; mt++)
        #pragma unroll
        for (int ks = 0; ks < 3; ks++) {
            const float* r0 = Ks + (w*32 + mt*16 + g)*QPAD + ks*8 + tig;
            const float* r1 = r0 + 8*QPAD;
            qa[mt][ks][0] = __float_as_uint(r0[0]);
            qa[mt][ks][1] = __float_as_uint(r1[0]);
            qa[mt][ks][2] = __float_as_uint(r0[4]);
            qa[mt][ks][3] = __float_as_uint(r1[4]);
        }

    // O accumulators: 4 n-tiles (3 V dims + ones-column carrying l)
    float o[2][4][4];
    #pragma unroll
    for (int mt = 0; mt < 2; mt++)
        #pragma unroll
        for (int dn = 0; dn < 4; dn++)
            #pragma unroll
            for (int j = 0; j < 4; j++) o[mt][dn][j] = 0.f;

    // ================= main loop over this split's key tiles =================
    #pragma unroll 1
    for (int kti = 0; kti < KT_PER; kti++) {
        const int kt = sp*KT_PER + kti;
        __syncthreads();   // previous tile's reads (or Q fragments) done
        {
            #pragma unroll
            for (int rr = 0; rr < 2; rr++) {
                int r = tid + rr*128;
                const float* ksrc = g_k + (size_t)(b*LL + kt*BK + r)*DD;
                uint32_t kdst = smb + (OFF_K + r*KPAD)*4;
                #pragma unroll
                for (int i = 0; i < 6; i++) cp16(kdst + i*16, ksrc + i*4);
            }
            const uint32_t* vsrc = g_vtp + (size_t)b*DD*(LL/2) + kt*(BK/2);
            #pragma unroll
            for (int i = 0; i < 6; i++) {
                int idx = tid + i*128;           // < 768
                int d = idx >> 5, c = idx & 31;
                cp16(smb + (OFF_V + d*VROW + c*4)*4, vsrc + (size_t)d*(LL/2) + c*4);
            }
            CP_COMMIT();
            CP_WAIT0();
        }
        __syncthreads();

        // ---- 4 chunks of 64 keys ----
        #pragma unroll 1
        for (int ck = 0; ck < 4; ck++) {
            float s[2][8][4];
            #pragma unroll
            for (int mt = 0; mt < 2; mt++)
                #pragma unroll
                for (int nt = 0; nt < 8; nt++)
                    #pragma unroll
                    for (int j = 0; j < 4; j++) s[mt][nt][j] = 0.f;

            // S = Q K^T (tf32), in log2 units
            #pragma unroll
            for (int nt = 0; nt < 8; nt++) {
                const float* kr = Ks + (ck*64 + nt*8 + g)*KPAD + tig;
                #pragma unroll
                for (int ks = 0; ks < 3; ks++) {
                    uint32_t b0 = __float_as_uint(kr[ks*8]);
                    uint32_t b1 = __float_as_uint(kr[ks*8 + 4]);
                    mma_tf32(s[0][nt], qa[0][ks], b0, b1);
                    mma_tf32(s[1][nt], qa[1][ks], b0, b1);
                }
            }

            // p = 2^s  (no max, no rescale)
            #pragma unroll
            for (int mt = 0; mt < 2; mt++)
                #pragma unroll
                for (int nt = 0; nt < 8; nt++)
                    #pragma unroll
                    for (int j = 0; j < 4; j++)
                        s[mt][nt][j] = ex2f(s[mt][nt][j]);

            // O += P V (bf16); n-tile 3 accumulates l via ones row
            #pragma unroll
            for (int ks2 = 0; ks2 < 4; ks2++) {
                uint32_t pa[2][4];
                #pragma unroll
                for (int mt = 0; mt < 2; mt++) {
                    pa[mt][0] = packbf(s[mt][ks2*2][1],   s[mt][ks2*2][0]);
                    pa[mt][1] = packbf(s[mt][ks2*2][3],   s[mt][ks2*2][2]);
                    pa[mt][2] = packbf(s[mt][ks2*2+1][1], s[mt][ks2*2+1][0]);
                    pa[mt][3] = packbf(s[mt][ks2*2+1][3], s[mt][ks2*2+1][2]);
                }
                const uint32_t* vr = Vb + g*VROW + ck*32 + ks2*8 + tig;
                #pragma unroll
                for (int dn = 0; dn < 4; dn++) {
                    uint32_t b0 = vr[dn*8*VROW];
                    uint32_t b1 = vr[dn*8*VROW + 4];
                    mma_bf16(o[0][dn], pa[0], b0, b1);
                    mma_bf16(o[1][dn], pa[1], b0, b1);
                }
            }
        }
    }

    // ---- bounce partials (stride 28) and write to g_part, coalesced ----
    __syncthreads();
    #pragma unroll
    for (int mt = 0; mt < 2; mt++)
        #pragma unroll
        for (int h = 0; h < 2; h++) {
            int row = w*32 + mt*16 + g + h*8;
            #pragma unroll
            for (int dn = 0; dn < 3; dn++) {
                sm[row*28 + dn*8 + 2*tig]     = o[mt][dn][h*2];
                sm[row*28 + dn*8 + 2*tig + 1] = o[mt][dn][h*2+1];
            }
            if (tig == 0) sm[row*28 + 24] = o[mt][3][h*2];   // l
        }
    __syncthreads();
    {
        float4* dst = reinterpret_cast<float4*>(g_part + ((size_t)sp*NTOK + b*LL + qt*BQ + tid)*28);
        const float4* srcb = reinterpret_cast<const float4*>(sm + tid*28);
        #pragma unroll
        for (int i = 0; i < 7; i++) dst[i] = srcb[i];
    }
}

// ---------------------------------------------------------------------------
// Kernel 3: combine splits + Wo/gamma/residual epilogue.
// ---------------------------------------------------------------------------
__global__ __launch_bounds__(128) void combine_kernel(
    const float* __restrict__ tensor, const float* __restrict__ wo,
    const float* __restrict__ gammap, float* __restrict__ out)
{
    __shared__ float Wos[DD*CH];      // 18432 B
    int tid = threadIdx.x;
    {
        float4* wd = reinterpret_cast<float4*>(Wos);
        const float4* ws = reinterpret_cast<const float4*>(wo);
        #pragma unroll
        for (int i = 0; i < 9; i++) wd[tid + i*128] = ws[tid + i*128];
    }
    __syncthreads();

    int tok = blockIdx.x * 128 + tid;
    float ov[28];
    {
        const float4* p0 = reinterpret_cast<const float4*>(g_part + (size_t)tok*28);
        const float4* p1 = reinterpret_cast<const float4*>(g_part + ((size_t)NTOK + tok)*28);
        #pragma unroll
        for (int i = 0; i < 7; i++) {
            float4 a = p0[i], c = p1[i];
            ov[i*4+0] = a.x + c.x;
            ov[i*4+1] = a.y + c.y;
            ov[i*4+2] = a.z + c.z;
            ov[i*4+3] = a.w + c.w;
        }
    }
    float inv = 1.0f / ov[24];
    float attn[DD];
    #pragma unroll
    for (int d = 0; d < DD; d++) attn[d] = ov[d] * inv;

    float gm = *gammap;
    const float4* tr = reinterpret_cast<const float4*>(tensor + (size_t)tok * CH);
    float4* orow = reinterpret_cast<float4*>(out + (size_t)tok * CH);
    const float4* wos = reinterpret_cast<const float4*>(Wos);

    #pragma unroll 1
    for (int c4 = 0; c4 < CH/4; c4++) {
        float4 t = tr[c4];
        float sx = 0.f, sy = 0.f, sz = 0.f, sw = 0.f;
        #pragma unroll
        for (int d = 0; d < DD; d++) {
            float4 wv4 = wos[d*48 + c4];
            sx = fmaf(attn[d], wv4.x, sx);
            sy = fmaf(attn[d], wv4.y, sy);
            sz = fmaf(attn[d], wv4.z, sz);
            sw = fmaf(attn[d], wv4.w, sw);
        }
        t.x = fmaf(gm, sx, t.x);
        t.y = fmaf(gm, sy, t.y);
        t.z = fmaf(gm, sz, t.z);
        t.w = fmaf(gm, sw, t.w);
        orow[c4] = t;
    }
}

extern "C" void kernel_launch(void* const* d_in, const int* in_sizes, int n_in,
                              void* d_out, int out_size)
{
    const float* tensor = (const float*)d_in[0];
    const float* wq     = (const float*)d_in[1];
    const float* wk     = (const float*)d_in[2];
    const float* wv     = (const float*)d_in[3];
    const float* wo     = (const float*)d_in[4];
    const float* gamma  = (const float*)d_in[5];
    float* out = (float*)d_out;

    cudaFuncSetAttribute(proj_kernel, cudaFuncAttributeMaxDynamicSharedMemorySize, 72*CH*4);
    cudaFuncSetAttribute(attn_mma_kernel, cudaFuncAttributeMaxDynamicSharedMemorySize, SM_FLOATS*4);

    proj_kernel<<<NTOK/128, 128, 72*CH*4>>>(tensor, wq, wk, wv);

    dim3 g2(LL/BQ, BB, NS);
    attn_mma_kernel<<<g2, 128, SM_FLOATS*4>>>();

    combine_kernel<<<NTOK/128, 128>>>(tensor, wo, gamma, out);
}

// round 10
// speedup vs baseline: 1.1899x; 1.1899x over previous
#include <cuda_runtime.h>
#include <cuda_bf16.h>
#include <cstdint>
#include <math.h>

#define CH 192
#define DD 24
#define BB 8
#define LL 4096
#define NTOK (BB*LL)
#define BQ 128
#define BK 256
#define NKT (LL/BK)

#define QPAD 28
#define KPAD 28
#define APAD 26
#define VROW 132                      // u32 words per d-row (128 + 4 pad)
#define LOG2E 1.4426950408889634f

// ---- proj smem layout (floats) ----
#define XP 52                         // padded row for X/Wt chunks
#define POFF_W 6656                   // Xs[128][52] then Wts[72][52]
#define P_FLOATS (POFF_W + 72*XP)     // 10400 floats = 41.6 KB (bounce reuses: 128*76=9728)

// ---- attn smem layout (floats) ----
#define OFF_Q 0                       // 128*28 = 3584
#define OFF_K 3584                    // 256*28 = 7168
#define OFF_V (3584+7168)             // 32*132 = 4224 words
#define SM_FLOATS (OFF_V + 4224)      // 14976 floats = 59904 B

__device__ float g_q[NTOK*DD];        // pre-scaled by log2(e)
__device__ float g_k[NTOK*DD];
__device__ uint32_t g_vtp[BB*DD*(LL/2)];   // [b][d][key/2] bf16x2 key-pair words

// ---------------------------------------------------------------------------
// helpers
// ---------------------------------------------------------------------------
__device__ __forceinline__ void mma_tf32(float* c, const uint32_t* a, uint32_t b0, uint32_t b1){
    asm volatile("mma.sync.aligned.m16n8k8.row.col.f32.tf32.tf32.f32 "
        "{%0,%1,%2,%3}, {%4,%5,%6,%7}, {%8,%9}, {%0,%1,%2,%3};"
        : "+f"(c[0]), "+f"(c[1]), "+f"(c[2]), "+f"(c[3])
        : "r"(a[0]), "r"(a[1]), "r"(a[2]), "r"(a[3]), "r"(b0), "r"(b1));
}
__device__ __forceinline__ void mma_bf16(float* c, const uint32_t* a, uint32_t b0, uint32_t b1){
    asm volatile("mma.sync.aligned.m16n8k16.row.col.f32.bf16.bf16.f32 "
        "{%0,%1,%2,%3}, {%4,%5,%6,%7}, {%8,%9}, {%0,%1,%2,%3};"
        : "+f"(c[0]), "+f"(c[1]), "+f"(c[2]), "+f"(c[3])
        : "r"(a[0]), "r"(a[1]), "r"(a[2]), "r"(a[3]), "r"(b0), "r"(b1));
}
__device__ __forceinline__ uint32_t packbf(float hi, float lo){
    uint32_t r;
    asm("cvt.rn.bf16x2.f32 %0, %1, %2;" : "=r"(r) : "f"(hi), "f"(lo));
    return r;
}
__device__ __forceinline__ float ex2f(float x){
    float y;
    asm("ex2.approx.f32 %0, %1;" : "=f"(y) : "f"(x));
    return y;
}
__device__ __forceinline__ uint32_t smem_u32(const void* p){
    uint32_t a;
    asm("{ .reg .u64 t; cvta.to.shared.u64 t, %1; cvt.u32.u64 %0, t; }":"=r"(a):"l"(p));
    return a;
}
__device__ __forceinline__ void cp16(uint32_t dst, const void* src){
    asm volatile("cp.async.ca.shared.global [%0], [%1], 16;"::"r"(dst),"l"(src):"memory");
}
#define CP_COMMIT() asm volatile("cp.async.commit_group;":::"memory")
#define CP_WAIT0()  asm volatile("cp.async.wait_group 0;":::"memory")

// ---------------------------------------------------------------------------
// Kernel 1: tf32 MMA QKV projection. C[128 tok x 72] = X[128x192] @ W[192x72].
// 4 warps x 32 tokens (2 m-tiles), 9 n-tiles, K chunked 4 x 48.
// Wq pre-scaled by log2(e). V written transposed+packed bf16 key-pair words.
// ---------------------------------------------------------------------------
__global__ __launch_bounds__(128) void proj_mma_kernel(
    const float* __restrict__ x, const float* __restrict__ wq,
    const float* __restrict__ wk, const float* __restrict__ wv)
{
    extern __shared__ float sm[];
    float* Xs  = sm;                 // [128][52]
    float* Wts = sm + POFF_W;        // [72][52]  (Wt[o][c])

    const int tid  = threadIdx.x;
    const int w    = tid >> 5;
    const int lane = tid & 31;
    const int g    = lane >> 2;
    const int tig  = lane & 3;
    const int tok0 = blockIdx.x * 128;

    float c[2][9][4];
    #pragma unroll
    for (int mt = 0; mt < 2; mt++)
        #pragma unroll
        for (int nt = 0; nt < 9; nt++)
            #pragma unroll
            for (int j = 0; j < 4; j++) c[mt][nt][j] = 0.f;

    #pragma unroll 1
    for (int ch = 0; ch < 4; ch++) {
        __syncthreads();
        // stage X chunk: row tid, 48 channels = 12 float4
        {
            const float4* xsrc = reinterpret_cast<const float4*>(x + (size_t)(tok0 + tid)*CH + ch*48);
            float4* xdst = reinterpret_cast<float4*>(Xs + tid*XP);
            #pragma unroll
            for (int i = 0; i < 12; i++) xdst[i] = xsrc[i];
        }
        // stage Wt chunk: Wt[o][cc] = W[ch*48+cc][o], q-rows scaled by log2(e)
        for (int i = tid; i < 72*48; i += 128) {
            int o = i / 48, cc = i - o*48;
            float val;
            if (o < 24)      val = wq[(ch*48 + cc)*DD + o] * LOG2E;
            else if (o < 48) val = wk[(ch*48 + cc)*DD + (o - 24)];
            else             val = wv[(ch*48 + cc)*DD + (o - 48)];
            Wts[o*XP + cc] = val;
        }
        __syncthreads();

        #pragma unroll
        for (int ks = 0; ks < 6; ks++) {
            uint32_t a[2][4];
            #pragma unroll
            for (int mt = 0; mt < 2; mt++) {
                const float* r0 = Xs + (w*32 + mt*16 + g)*XP + ks*8 + tig;
                const float* r1 = r0 + 8*XP;
                a[mt][0] = __float_as_uint(r0[0]);
                a[mt][1] = __float_as_uint(r1[0]);
                a[mt][2] = __float_as_uint(r0[4]);
                a[mt][3] = __float_as_uint(r1[4]);
            }
            #pragma unroll
            for (int nt = 0; nt < 9; nt++) {
                const float* br = Wts + (nt*8 + g)*XP + ks*8 + tig;
                uint32_t b0 = __float_as_uint(br[0]);
                uint32_t b1 = __float_as_uint(br[4]);
                mma_tf32(c[0][nt], a[0], b0, b1);
                mma_tf32(c[1][nt], a[1], b0, b1);
            }
        }
    }

    // ---- bounce C to smem [128][76] ----
    __syncthreads();
    #pragma unroll
    for (int mt = 0; mt < 2; mt++)
        #pragma unroll
        for (int h = 0; h < 2; h++) {
            int row = w*32 + mt*16 + g + h*8;
            #pragma unroll
            for (int nt = 0; nt < 9; nt++) {
                sm[row*76 + nt*8 + 2*tig]     = c[mt][nt][h*2];
                sm[row*76 + nt*8 + 2*tig + 1] = c[mt][nt][h*2+1];
            }
        }
    __syncthreads();

    // ---- q, k out (row tid) ----
    {
        int tok = tok0 + tid;
        float4* qo = reinterpret_cast<float4*>(g_q + (size_t)tok * DD);
        float4* ko = reinterpret_cast<float4*>(g_k + (size_t)tok * DD);
        const float* r = sm + tid*76;
        #pragma unroll
        for (int i = 0; i < 6; i++) {
            qo[i] = make_float4(r[i*4+0],    r[i*4+1],    r[i*4+2],    r[i*4+3]);
            ko[i] = make_float4(r[24+i*4+0], r[24+i*4+1], r[24+i*4+2], r[24+i*4+3]);
        }
    }
    // ---- V packed: dst[d][p] = {lo=V[2p][d], hi=V[2p+1][d]} ----
    {
        int b0i  = tok0 / LL;
        int koff = (tok0 - b0i*LL) / 2;
        uint32_t* dst = g_vtp + (size_t)b0i*DD*(LL/2) + koff;
        #pragma unroll
        for (int i = 0; i < 12; i++) {
            int idx = tid + i*128;       // < 1536
            int d = idx >> 6, p = idx & 63;
            dst[(size_t)d*(LL/2) + p] = packbf(sm[(2*p+1)*76 + 48 + d], sm[(2*p)*76 + 48 + d]);
        }
    }
}

// ---------------------------------------------------------------------------
// Kernel 2: mma.sync flash attention, max-free softmax (p = ex2(s), log2e
// pre-folded into Wq; l via ones-column in V). 4 warps x 32 queries.
// ---------------------------------------------------------------------------
__global__ __launch_bounds__(128, 3) void attn_mma_kernel(
    const float* __restrict__ tensor, const float* __restrict__ wo,
    const float* __restrict__ gammap, float* __restrict__ out)
{
    extern __shared__ float sm[];
    float* Qs = sm + OFF_Q;
    float* Ks = sm + OFF_K;
    uint32_t* Vbw = reinterpret_cast<uint32_t*>(sm + OFF_V);
    const uint32_t* Vb = Vbw;
    const uint32_t smb = smem_u32(sm);

    const int tid  = threadIdx.x;
    const int w    = tid >> 5;
    const int lane = tid & 31;
    const int g    = lane >> 2;
    const int tig  = lane & 3;
    const int qt = blockIdx.x, b = blockIdx.y;

    // ---- stage Q tile (already log2e-scaled) ----
    {
        const float4* src = reinterpret_cast<const float4*>(g_q + (size_t)(b*LL + qt*BQ + tid)*DD);
        float4* dst = reinterpret_cast<float4*>(Qs + tid*QPAD);
        #pragma unroll
        for (int i = 0; i < 6; i++) dst[i] = src[i];
    }
    // ---- static V rows 24..31: zero, then row 24 cols 0..127 = bf16 ones ----
    for (int i = tid; i < 8*VROW; i += 128) Vbw[24*VROW + i] = 0;
    Vbw[24*VROW + tid] = 0x3F803F80u;
    __syncthreads();

    // ---- Q fragments: warp owns 32 rows (2 m-tiles) ----
    uint32_t qa[2][3][4];
    #pragma unroll
    for (int mt = 0; mt < 2; mt++)
        #pragma unroll
        for (int ks = 0; ks < 3; ks++) {
            const float* r0 = Qs + (w*32 + mt*16 + g)*QPAD + ks*8 + tig;
            const float* r1 = r0 + 8*QPAD;
            qa[mt][ks][0] = __float_as_uint(r0[0]);
            qa[mt][ks][1] = __float_as_uint(r1[0]);
            qa[mt][ks][2] = __float_as_uint(r0[4]);
            qa[mt][ks][3] = __float_as_uint(r1[4]);
        }

    // O accumulators: 4 n-tiles (3 V dims + ones-column carrying l)
    float o[2][4][4];
    #pragma unroll
    for (int mt = 0; mt < 2; mt++)
        #pragma unroll
        for (int dn = 0; dn < 4; dn++)
            #pragma unroll
            for (int j = 0; j < 4; j++) o[mt][dn][j] = 0.f;

    // ================= main loop =================
    #pragma unroll 1
    for (int kt = 0; kt < NKT; kt++) {
        __syncthreads();
        {
            #pragma unroll
            for (int rr = 0; rr < 2; rr++) {
                int r = tid + rr*128;
                const float* ksrc = g_k + (size_t)(b*LL + kt*BK + r)*DD;
                uint32_t kdst = smb + (OFF_K + r*KPAD)*4;
                #pragma unroll
                for (int i = 0; i < 6; i++) cp16(kdst + i*16, ksrc + i*4);
            }
            const uint32_t* vsrc = g_vtp + (size_t)b*DD*(LL/2) + kt*(BK/2);
            #pragma unroll
            for (int i = 0; i < 6; i++) {
                int idx = tid + i*128;           // < 768
                int d = idx >> 5, cc = idx & 31;
                cp16(smb + (OFF_V + d*VROW + cc*4)*4, vsrc + (size_t)d*(LL/2) + cc*4);
            }
            CP_COMMIT();
            CP_WAIT0();
        }
        __syncthreads();

        // ---- 4 chunks of 64 keys ----
        #pragma unroll 1
        for (int ck = 0; ck < 4; ck++) {
            float s[2][8][4];
            #pragma unroll
            for (int mt = 0; mt < 2; mt++)
                #pragma unroll
                for (int nt = 0; nt < 8; nt++)
                    #pragma unroll
                    for (int j = 0; j < 4; j++) s[mt][nt][j] = 0.f;

            // S = Q K^T (tf32), in log2 units
            #pragma unroll
            for (int nt = 0; nt < 8; nt++) {
                const float* kr = Ks + (ck*64 + nt*8 + g)*KPAD + tig;
                #pragma unroll
                for (int ks = 0; ks < 3; ks++) {
                    uint32_t b0 = __float_as_uint(kr[ks*8]);
                    uint32_t b1 = __float_as_uint(kr[ks*8 + 4]);
                    mma_tf32(s[0][nt], qa[0][ks], b0, b1);
                    mma_tf32(s[1][nt], qa[1][ks], b0, b1);
                }
            }

            // p = 2^s  (no max, no rescale)
            #pragma unroll
            for (int mt = 0; mt < 2; mt++)
                #pragma unroll
                for (int nt = 0; nt < 8; nt++)
                    #pragma unroll
                    for (int j = 0; j < 4; j++)
                        s[mt][nt][j] = ex2f(s[mt][nt][j]);

            // O += P V (bf16); n-tile 3 accumulates l via ones row
            #pragma unroll
            for (int ks2 = 0; ks2 < 4; ks2++) {
                uint32_t pa[2][4];
                #pragma unroll
                for (int mt = 0; mt < 2; mt++) {
                    pa[mt][0] = packbf(s[mt][ks2*2][1],   s[mt][ks2*2][0]);
                    pa[mt][1] = packbf(s[mt][ks2*2][3],   s[mt][ks2*2][2]);
                    pa[mt][2] = packbf(s[mt][ks2*2+1][1], s[mt][ks2*2+1][0]);
                    pa[mt][3] = packbf(s[mt][ks2*2+1][3], s[mt][ks2*2+1][2]);
                }
                const uint32_t* vr = Vb + g*VROW + ck*32 + ks2*8 + tig;
                #pragma unroll
                for (int dn = 0; dn < 4; dn++) {
                    uint32_t b0 = vr[dn*8*VROW];
                    uint32_t b1 = vr[dn*8*VROW + 4];
                    mma_bf16(o[0][dn], pa[0], b0, b1);
                    mma_bf16(o[1][dn], pa[1], b0, b1);
                }
            }
        }
    }

    // ---- write normalized attn (transpose bounce), stage Wo into K area ----
    __syncthreads();
    {
        #pragma unroll
        for (int mt = 0; mt < 2; mt++)
            #pragma unroll
            for (int h = 0; h < 2; h++) {
                float lv = __shfl_sync(0xffffffffu, o[mt][3][h*2], lane & 28);
                float inv = 1.0f / lv;
                int row = w*32 + mt*16 + g + h*8;
                #pragma unroll
                for (int dn = 0; dn < 3; dn++) {
                    sm[row*APAD + dn*8 + 2*tig]     = o[mt][dn][h*2]   * inv;
                    sm[row*APAD + dn*8 + 2*tig + 1] = o[mt][dn][h*2+1] * inv;
                }
            }
        float4* wd = reinterpret_cast<float4*>(Ks);
        const float4* ws = reinterpret_cast<const float4*>(wo);
        #pragma unroll
        for (int i = 0; i < 9; i++) wd[tid + i*128] = ws[tid + i*128];
    }
    __syncthreads();

    // ---- epilogue: out = tensor + gamma * attn @ Wo ----
    float attn[DD];
    #pragma unroll
    for (int d = 0; d < DD; d++) attn[d] = sm[tid*APAD + d];

    float gm = *gammap;
    int tok = b*LL + qt*BQ + tid;
    const float4* tr = reinterpret_cast<const float4*>(tensor + (size_t)tok * CH);
    float4* orow = reinterpret_cast<float4*>(out + (size_t)tok * CH);
    const float4* wos = reinterpret_cast<const float4*>(Ks);

    #pragma unroll 1
    for (int c4 = 0; c4 < CH/4; c4++) {
        float4 t = tr[c4];
        float sx = 0.f, sy = 0.f, sz = 0.f, sw = 0.f;
        #pragma unroll
        for (int d = 0; d < DD; d++) {
            float4 wv4 = wos[d*48 + c4];
            sx = fmaf(attn[d], wv4.x, sx);
            sy = fmaf(attn[d], wv4.y, sy);
            sz = fmaf(attn[d], wv4.z, sz);
            sw = fmaf(attn[d], wv4.w, sw);
        }
        t.x = fmaf(gm, sx, t.x);
        t.y = fmaf(gm, sy, t.y);
        t.z = fmaf(gm, sz, t.z);
        t.w = fmaf(gm, sw, t.w);
        orow[c4] = t;
    }
}

extern "C" void kernel_launch(void* const* d_in, const int* in_sizes, int n_in,
                              void* d_out, int out_size)
{
    const float* tensor = (const float*)d_in[0];
    const float* wq     = (const float*)d_in[1];
    const float* wk     = (const float*)d_in[2];
    const float* wv     = (const float*)d_in[3];
    const float* wo     = (const float*)d_in[4];
    const float* gamma  = (const float*)d_in[5];
    float* out = (float*)d_out;

    cudaFuncSetAttribute(attn_mma_kernel, cudaFuncAttributeMaxDynamicSharedMemorySize, SM_FLOATS*4);

    proj_mma_kernel<<<NTOK/128, 128, P_FLOATS*4>>>(tensor, wq, wk, wv);

    dim3 g2(LL/BQ, BB);
    attn_mma_kernel<<<g2, 128, SM_FLOATS*4>>>(tensor, wo, gamma, out);
}